// round 1
// baseline (speedup 1.0000x reference)
#include <cuda_runtime.h>

#define BB 20
#define LL 20
#define VV 100000

// Single-block kernel:
//  Phase 1: gather P[b][j][k] = topic_prob[b, j, clip(hard_label[b,k])] into smem (8000 loads).
//  Phase 2: one warp per batch computes the (L+1)x(L+1) DP via anti-diagonal
//           wavefront: lane k owns DP column k+1; neighbor values (left, diag)
//           come from lane k-1 via shfl_up of its (prev, prevprev) registers.
//  Phase 3: per-batch loss -> shared atomicAdd -> out[0] = sum / B.
__global__ void __launch_bounds__(640) calcs_kernel(
    const float* __restrict__ topic_prob,
    const int*   __restrict__ hard_label,
    float*       __restrict__ out)
{
    __shared__ int   s_label[BB * LL];
    __shared__ float s_P[BB * LL * LL];   // [b][j][k], k contiguous
    __shared__ float s_sum;

    const int tid = threadIdx.x;
    if (tid == 0) s_sum = 0.0f;

    // labels to smem
    for (int i = tid; i < BB * LL; i += blockDim.x)
        s_label[i] = hard_label[i];
    __syncthreads();

    // gather phase: 8000 scattered loads, ~12.5 per thread (high MLP)
    for (int i = tid; i < BB * LL * LL; i += blockDim.x) {
        int b = i / (LL * LL);
        int j = (i / LL) % LL;
        int k = i % LL;
        int lab = s_label[b * LL + k];
        int idx = lab < 0 ? 0 : (lab > (VV - 1) ? (VV - 1) : lab);
        s_P[i] = topic_prob[(size_t)(b * LL + j) * VV + idx];
    }
    __syncthreads();

    const int warp = tid >> 5;
    const int lane = tid & 31;

    if (warp < BB && lane < LL) {
        const unsigned MASK = 0x000FFFFFu;  // lanes 0..19
        const int b = warp;

        const int   lab_k = s_label[b * LL + lane];
        const float mk    = (lab_k >= 0) ? 1.0f : 0.0f;
        const unsigned bal = __ballot_sync(MASK, lab_k >= 0);
        const int   len   = __popc(bal);     // sum of mask == gts_len

        // lane k computes cells (j, k+1) for j=1..L at wavefront step t=j+(k+1).
        // prev     = dp[j_last][k+1]   (this lane's most recent value)
        // prevprev = dp[j_last-1][k+1]
        float prev = 0.0f, prevprev = 0.0f, result = 0.0f;

        #pragma unroll
        for (int t = 2; t <= 2 * LL; ++t) {
            // neighbor column (k) values as of end of previous step:
            float left = __shfl_up_sync(MASK, prev, 1);      // dp[j][k]
            float diag = __shfl_up_sync(MASK, prevprev, 1);  // dp[j-1][k]
            if (lane == 0) { left = 0.0f; diag = 0.0f; }     // dp[*][0] = 0

            const int  j = t - 1 - lane;                     // row this lane computes now
            const bool active = (j >= 1) && (j <= LL);
            if (active) {
                const float p  = s_P[(b * LL + (j - 1)) * LL + lane];
                const float mj = (s_label[b * LL + (j - 1)] >= 0) ? 1.0f : 0.0f;
                const float up = prev;                       // dp[j-1][k+1]
                float val = p * (diag + 1.0f) + (1.0f - p) * fmaxf(left, up);
                val = (mj * mk > 0.0f) ? val : 0.0f;
                prevprev = prev;
                prev     = val;
                if (j == len && (lane + 1) == len) result = val;
            }
            // inactive lanes keep prev/prevprev frozen: exactly the boundary /
            // final-row values their right neighbor still needs.
        }

        if (len > 0 && (lane + 1) == len) {
            float calcs = -logf(result / (float)len);
            atomicAdd(&s_sum, calcs);
        }
    }
    __syncthreads();
    if (tid == 0) out[0] = s_sum * (1.0f / (float)BB);
}

extern "C" void kernel_launch(void* const* d_in, const int* in_sizes, int n_in,
                              void* d_out, int out_size) {
    const float* topic_prob = (const float*)d_in[0];
    const int*   hard_label = (const int*)d_in[1];
    float*       out        = (float*)d_out;
    calcs_kernel<<<1, 640>>>(topic_prob, hard_label, out);
}

// round 2
// speedup vs baseline: 1.1029x; 1.1029x over previous
#include <cuda_runtime.h>

#define BB 20
#define LL 20
#define VV 100000

// One block, 640 threads = 20 warps; warp b owns batch b.
//  Phase 1 (per-warp): lane k (k<20) loads hard_label[b][k], then its full P
//    column topic_prob[b, j, idx_k] for j=0..19 into registers (unrolled ->
//    20 outstanding LDGs, ONE latency trip), stores to smem s_P[b][j][k].
//  Phase 2 (per-warp): anti-diagonal wavefront DP. Lane k owns DP column k+1;
//    left/diag neighbors arrive via shfl_up of (prev, prevprev).
//  Phase 3: per-warp loss -> s_loss[b]; block sync; warp 0 shfl-reduces.
__global__ void __launch_bounds__(640) calcs_kernel(
    const float* __restrict__ topic_prob,
    const int*   __restrict__ hard_label,
    float*       __restrict__ out)
{
    __shared__ float s_P[BB][LL][LL];   // [b][j][k]
    __shared__ float s_loss[BB];

    const int tid  = threadIdx.x;
    const int warp = tid >> 5;
    const int lane = tid & 31;
    const unsigned MASK = 0x000FFFFFu;   // lanes 0..19

    if (warp < BB && lane < LL) {
        const int b = warp;

        // ---- label + full-column gather, max MLP ----
        const int lab = __ldg(&hard_label[b * LL + lane]);
        const unsigned bal = __ballot_sync(MASK, lab >= 0);
        const int len = __popc(bal);                       // gts_len
        const int idx = lab < 0 ? 0 : (lab > (VV - 1) ? (VV - 1) : lab);

        const float* col = topic_prob + (size_t)b * LL * VV + idx;
        float pj[LL];
        #pragma unroll
        for (int j = 0; j < LL; ++j)
            pj[j] = __ldg(col + (size_t)j * VV);           // 20 independent LDGs
        #pragma unroll
        for (int j = 0; j < LL; ++j)
            s_P[b][j][lane] = pj[j];
        __syncwarp(MASK);

        // ---- wavefront DP ----
        // lane k computes cell (j, k+1) at step t = j + k + 1.
        float prev = 0.0f, prevprev = 0.0f, result = 0.0f;

        #pragma unroll
        for (int t = 2; t <= 2 * LL; ++t) {
            float left = __shfl_up_sync(MASK, prev, 1);      // dp[j][k]
            float diag = __shfl_up_sync(MASK, prevprev, 1);  // dp[j-1][k]
            if (lane == 0) { left = 0.0f; diag = 0.0f; }     // dp[*][0] = 0

            const int j = t - 1 - lane;
            if (j >= 1 && j <= LL) {
                const float p = s_P[b][j - 1][lane];         // addr indep of shfl chain
                const float up = prev;                       // dp[j-1][k+1]
                float val = p * (diag + 1.0f) + (1.0f - p) * fmaxf(left, up);
                // cell kept only if mask[j-1] && mask[lane]
                const bool keep = ((bal >> (j - 1)) & (bal >> lane) & 1u) != 0u;
                val = keep ? val : 0.0f;
                prevprev = prev;
                prev     = val;
                if (j == len && (lane + 1) == len) result = val;
            }
            // inactive lanes freeze prev/prevprev = exactly the boundary values
            // their right neighbor still needs.
        }

        if (len > 0) {
            if ((lane + 1) == len)
                s_loss[b] = -logf(result / (float)len);
        } else if (lane == 0) {
            s_loss[b] = -logf(0.0f / 0.0f);                  // matches 0/0 -> nan path
        }
    }
    __syncthreads();

    // ---- final reduction: warp 0, lanes 0..19 ----
    if (warp == 0) {
        float v = (lane < BB) ? s_loss[lane] : 0.0f;
        #pragma unroll
        for (int off = 16; off > 0; off >>= 1)
            v += __shfl_down_sync(0xFFFFFFFFu, v, off);
        if (lane == 0) out[0] = v * (1.0f / (float)BB);
    }
}

extern "C" void kernel_launch(void* const* d_in, const int* in_sizes, int n_in,
                              void* d_out, int out_size) {
    const float* topic_prob = (const float*)d_in[0];
    const int*   hard_label = (const int*)d_in[1];
    float*       out        = (float*)d_out;
    calcs_kernel<<<1, 640>>>(topic_prob, hard_label, out);
}

// round 3
// speedup vs baseline: 1.3120x; 1.1895x over previous
#include <cuda_runtime.h>

#define BB 20
#define LL 20
#define VV 100000
#define NP (BB * LL * LL)   // 8000 gathered elements

// Scratch for the gathered P matrix (32 KB). __device__ global: allowed
// (no dynamic allocation).
__device__ float g_P[NP];

// ---------------------------------------------------------------------------
// Kernel A: distributed gather. One thread per element, spread over ~125
// blocks so the 8000 scattered 128B-line accesses are distributed across SMs
// instead of serializing through a single SM's L1tex wavefront queue.
// ---------------------------------------------------------------------------
__global__ void __launch_bounds__(64) gather_kernel(
    const float* __restrict__ topic_prob,
    const int*   __restrict__ hard_label)
{
    const int i = blockIdx.x * 64 + threadIdx.x;
    if (i < NP) {
        const int b = i / (LL * LL);
        const int j = (i / LL) % LL;
        const int k = i % LL;
        const int lab = __ldg(&hard_label[b * LL + k]);
        const int idx = lab < 0 ? 0 : (lab > (VV - 1) ? (VV - 1) : lab);
        g_P[i] = __ldg(&topic_prob[(size_t)(b * LL + j) * VV + idx]);
    }
}

// ---------------------------------------------------------------------------
// Kernel B: DP + reduction. Loads g_P contiguously (L2-hot), then one warp
// per batch runs the anti-diagonal wavefront. One shfl per step:
// diag_t == left_{t-1}, so the previous step's left is reused as diag.
// ---------------------------------------------------------------------------
__global__ void __launch_bounds__(640) dp_kernel(
    const int* __restrict__ hard_label,
    float*     __restrict__ out)
{
    __shared__ float s_P[NP];      // [b][j][k], k contiguous
    __shared__ float s_loss[BB];

    const int tid  = threadIdx.x;
    const int warp = tid >> 5;
    const int lane = tid & 31;
    const unsigned MASK = 0x000FFFFFu;   // lanes 0..19

    // contiguous vectorized copy of scratch -> smem (2000 float4 elements)
    {
        const float4* __restrict__ src = (const float4*)g_P;
        float4* dst = (float4*)s_P;
        #pragma unroll
        for (int i = tid; i < NP / 4; i += 640)
            dst[i] = src[i];
    }

    // per-warp label load + mask ballot (overlaps with the copy above)
    int lab = 0;
    unsigned bal = 0;
    int len = 0;
    if (warp < BB && lane < LL) {
        lab = __ldg(&hard_label[warp * LL + lane]);
        bal = __ballot_sync(MASK, lab >= 0);
        len = __popc(bal);
    }
    __syncthreads();

    if (warp < BB && lane < LL) {
        const int b = warp;
        // lane k computes cell (j, k+1) at wavefront step t = j + k + 1.
        float prev = 0.0f, prevprev = 0.0f, dleft = 0.0f, result = 0.0f;

        #pragma unroll
        for (int t = 2; t <= 2 * LL; ++t) {
            float left = __shfl_up_sync(MASK, prev, 1);   // dp[t-1-k][k]
            if (lane == 0) left = 0.0f;                   // dp[*][0] = 0
            const float diag = dleft;                     // dp[t-2-k][k]

            const int j = t - 1 - lane;
            if (j >= 1 && j <= LL) {
                const float p  = s_P[(b * LL + (j - 1)) * LL + lane];
                const float up = prev;                    // dp[j-1][k+1]
                const float M  = fmaxf(left, up);
                float val = fmaf(p, diag + 1.0f - M, M);  // p*(diag+1)+(1-p)*M
                const bool keep = ((bal >> (j - 1)) & (bal >> lane) & 1u) != 0u;
                val = keep ? val : 0.0f;
                prevprev = prev;
                prev     = val;
                if (j == len && (lane + 1) == len) result = val;
            }
            dleft = left;
            // inactive lanes freeze prev/prevprev = exactly the boundary
            // values their right neighbor still needs.
        }

        if (len > 0) {
            if ((lane + 1) == len)
                s_loss[b] = -logf(result / (float)len);
        } else if (lane == 0) {
            s_loss[b] = -logf(0.0f / 0.0f);               // 0/0 -> nan path
        }
    }
    __syncthreads();

    // final reduction: warp 0
    if (warp == 0) {
        float v = (lane < BB) ? s_loss[lane] : 0.0f;
        #pragma unroll
        for (int off = 16; off > 0; off >>= 1)
            v += __shfl_down_sync(0xFFFFFFFFu, v, off);
        if (lane == 0) out[0] = v * (1.0f / (float)BB);
    }
}

extern "C" void kernel_launch(void* const* d_in, const int* in_sizes, int n_in,
                              void* d_out, int out_size) {
    const float* topic_prob = (const float*)d_in[0];
    const int*   hard_label = (const int*)d_in[1];
    float*       out        = (float*)d_out;
    gather_kernel<<<(NP + 63) / 64, 64>>>(topic_prob, hard_label);
    dp_kernel<<<1, 640>>>(hard_label, out);
}

// round 4
// speedup vs baseline: 1.6014x; 1.2206x over previous
#include <cuda_runtime.h>

#define BB 20
#define LL 20
#define VV 100000
#define NP (BB * LL * LL)   // 8000 gathered elements

__device__ float g_P[NP];   // scratch for gathered P (32 KB)

// ---------------------------------------------------------------------------
// Kernel A: distributed gather across ~125 blocks (spreads the 8000 scattered
// 128B-line accesses over many SMs' L1tex queues).
// ---------------------------------------------------------------------------
__global__ void __launch_bounds__(64) gather_kernel(
    const float* __restrict__ topic_prob,
    const int*   __restrict__ hard_label)
{
    const int i = blockIdx.x * 64 + threadIdx.x;
    if (i < NP) {
        const int b = i / (LL * LL);
        const int j = (i / LL) % LL;
        const int k = i % LL;
        const int lab = __ldg(&hard_label[b * LL + k]);
        const int idx = lab < 0 ? 0 : (lab > (VV - 1) ? (VV - 1) : lab);
        g_P[i] = __ldg(&topic_prob[(size_t)(b * LL + j) * VV + idx]);
    }
}

// ---------------------------------------------------------------------------
// Kernel B: DP. 10 warps; warp w handles batches 2w (lanes 0-15) and 2w+1
// (lanes 16-31). Within a 16-lane segment, lane c (c<10) owns DP columns
// kA=2c+1, kB=2c+2. Anti-diagonal wavefront: at step t lane c computes row
// j=t-c for both its columns. One segmented shfl per step carries the
// neighbor's kB column value; diag is the previous step's shfl (dleft).
// P addresses are affine in t: base + t*20 floats -> LDS.64 [R+imm].
// ---------------------------------------------------------------------------
#define PAD_LO 288
#define PAD_HI 192

__global__ void __launch_bounds__(320) dp_kernel(
    const int* __restrict__ hard_label,
    float*     __restrict__ out)
{
    __shared__ float4 s_buf4[(PAD_LO + NP + PAD_HI) / 4];
    float* s_P = ((float*)s_buf4) + PAD_LO;
    __shared__ float s_loss[BB];

    const int tid  = threadIdx.x;
    const int warp = tid >> 5;
    const int lane = tid & 31;
    const int sub  = lane & 15;          // position within 16-lane segment
    const int half = lane >> 4;          // 0 or 1

    // contiguous vectorized copy g_P -> smem (L2-hot after kernel A)
    {
        const float4* __restrict__ src = (const float4*)g_P;
        float4* dst = (float4*)s_P;
        #pragma unroll
        for (int i = tid; i < NP / 4; i += 320)
            dst[i] = src[i];
    }

    // masks for both batches of this warp
    const int b0 = 2 * warp, b1 = 2 * warp + 1;
    int l0 = (lane < LL) ? __ldg(&hard_label[b0 * LL + lane]) : -1;
    const unsigned bal0 = __ballot_sync(0xFFFFFFFFu, (lane < LL) && (l0 >= 0));
    int l1 = (lane < LL) ? __ldg(&hard_label[b1 * LL + lane]) : -1;
    const unsigned bal1 = __ballot_sync(0xFFFFFFFFu, (lane < LL) && (l1 >= 0));

    const unsigned bal = half ? bal1 : bal0;
    const int len = __popc(bal & 0xFFFFFu);
    const int b   = half ? b1 : b0;
    const int c   = sub;

    __syncthreads();

    // per-lane constants
    const int  base  = b * (LL * LL) - 18 * c - LL;   // s_P index at t=0
    const bool capA  = (2 * c + 1 == len);
    const bool capB  = (2 * c + 2 == len);
    const bool valid = (c < 10);

    float prevA = 0.0f, prevB = 0.0f, dleft = 0.0f, result = 0.0f;

    if (bal0 == 0xFFFFFu && bal1 == 0xFFFFFu) {
        // ---- fast path: all masks = 1 (always in practice) ----
        #pragma unroll
        for (int t = 1; t <= LL + 9; ++t) {
            float left = __shfl_up_sync(0xFFFFFFFFu, prevB, 1, 16);
            if (sub == 0) left = 0.0f;
            const float diag = dleft;
            dleft = left;

            const int  j   = t - c;
            const bool act = valid && (j >= 1) && (j <= LL);

            const float2 p2 = *(const float2*)(s_P + base + t * LL);

            const float Ma = fmaxf(left, prevA);
            const float vA = fmaf(p2.x, diag + 1.0f - Ma, Ma);
            const float Mb = fmaxf(vA, prevB);
            const float vB = fmaf(p2.y, prevA + 1.0f - Mb, Mb);

            if (act) {
                if (j == len) {
                    if (capA) result = vA;
                    if (capB) result = vB;
                }
                prevA = vA;
                prevB = vB;
            }
        }
    } else {
        // ---- general path: per-cell mask zeroing ----
        const unsigned bitA = (bal >> (2 * c)) & 1u;
        const unsigned bitB = (bal >> (2 * c + 1)) & 1u;
        #pragma unroll
        for (int t = 1; t <= LL + 9; ++t) {
            float left = __shfl_up_sync(0xFFFFFFFFu, prevB, 1, 16);
            if (sub == 0) left = 0.0f;
            const float diag = dleft;
            dleft = left;

            const int  j   = t - c;
            const bool act = valid && (j >= 1) && (j <= LL);
            const int  js  = (j < 1) ? 1 : (j > LL ? LL : j);
            const unsigned mj = (bal >> (js - 1)) & 1u;

            const float2 p2 = *(const float2*)(s_P + base + t * LL);

            const float Ma = fmaxf(left, prevA);
            float vA = fmaf(p2.x, diag + 1.0f - Ma, Ma);
            vA = (mj & bitA) ? vA : 0.0f;
            const float Mb = fmaxf(vA, prevB);
            float vB = fmaf(p2.y, prevA + 1.0f - Mb, Mb);
            vB = (mj & bitB) ? vB : 0.0f;

            if (act) {
                if (j == len) {
                    if (capA) result = vA;
                    if (capB) result = vB;
                }
                prevA = vA;
                prevB = vB;
            }
        }
    }

    // per-batch loss
    if (len > 0) {
        if ((capA || capB) && valid)
            s_loss[b] = -logf(result / (float)len);
    } else if (sub == 0) {
        s_loss[b] = -logf(0.0f / 0.0f);   // 0/0 -> nan, matches reference
    }
    __syncthreads();

    // final reduction: warp 0
    if (warp == 0) {
        float v = (lane < BB) ? s_loss[lane] : 0.0f;
        #pragma unroll
        for (int off = 16; off > 0; off >>= 1)
            v += __shfl_down_sync(0xFFFFFFFFu, v, off);
        if (lane == 0) out[0] = v * (1.0f / (float)BB);
    }
}

extern "C" void kernel_launch(void* const* d_in, const int* in_sizes, int n_in,
                              void* d_out, int out_size) {
    const float* topic_prob = (const float*)d_in[0];
    const int*   hard_label = (const int*)d_in[1];
    float*       out        = (float*)d_out;
    gather_kernel<<<(NP + 63) / 64, 64>>>(topic_prob, hard_label);
    dp_kernel<<<1, 320>>>(hard_label, out);
}